// round 16
// baseline (speedup 1.0000x reference)
#include <cuda_runtime.h>
#include <cuda_bf16.h>
#include <math.h>
#include <stdint.h>

#define HW 16384
#define C  768
#define EPSF 1e-8f

#define NJT   128       // j-tiles of 128 cols
#define NCHK  24        // k chunks of 32
#define ASTR  1552      // A_s row stride bytes (768*2 + 16 pad -> conflict-free ldmatrix)
#define ASZ   (128 * ASTR)          // 198656
#define BSTR  272       // B_s row stride bytes (128*2 + 16 pad)
#define BCHK  (32 * BSTR)           // 8704 per buffer
#define SM_B0 ASZ
#define SM_B1 (ASZ + BCHK)
#define SM_RED (ASZ + 2 * BCHK)     // reduction area: 512 best + 512 j
#define SMEM_TOTAL (SM_RED + 512 * 8)

// ---------------- scratch ------------------------------------------------------
__device__ __align__(16) __nv_bfloat16 g_bbf[(size_t)C * HW];  // B in bf16, [k][j]
__device__ float g_pa[6][HW];
__device__ float g_pb[6][HW];
__device__ float g_rna_cos[HW];
__device__ float g_rnb_cos[HW];
__device__ float g_rnb_nn[HW];
__device__ int   g_bjf[HW];
__device__ float g_li[HW];

static __device__ __forceinline__ uint32_t smem_u32(const void* p) {
    uint32_t a;
    asm("{ .reg .u64 t; cvta.to.shared.u64 t, %1; cvt.u32.u64 %0, t; }" : "=r"(a) : "l"(p));
    return a;
}

// ---------------- prep: convert B->bf16 + norm partials (float2 over j) --------
__global__ void prep_kernel(const float* __restrict__ A, const float* __restrict__ B) {
    int j = (blockIdx.x * 256 + threadIdx.x) * 2;
    int kb = blockIdx.y;
    float sa0 = 0.f, sa1 = 0.f, sb0 = 0.f, sb1 = 0.f;
#pragma unroll 8
    for (int kk = 0; kk < 128; ++kk) {
        int k = kb * 128 + kk;
        float2 av = *(const float2*)(A + (size_t)k * HW + j);
        float2 bv = *(const float2*)(B + (size_t)k * HW + j);
        sa0 = fmaf(av.x, av.x, sa0);
        sa1 = fmaf(av.y, av.y, sa1);
        sb0 = fmaf(bv.x, bv.x, sb0);
        sb1 = fmaf(bv.y, bv.y, sb1);
        __nv_bfloat162 h = __floats2bfloat162_rn(bv.x, bv.y);
        *(uint32_t*)(g_bbf + (size_t)k * HW + j) = *reinterpret_cast<uint32_t*>(&h);
    }
    g_pa[kb][j] = sa0; g_pa[kb][j + 1] = sa1;
    g_pb[kb][j] = sb0; g_pb[kb][j + 1] = sb1;
}

__global__ void norms_fin_kernel() {
    int j = blockIdx.x * 256 + threadIdx.x;
    float sa = 0.f, sb = 0.f;
#pragma unroll
    for (int kb = 0; kb < 6; ++kb) { sa += g_pa[kb][j]; sb += g_pb[kb][j]; }
    g_rna_cos[j] = 1.f / (sqrtf(sa) + EPSF);
    g_rnb_cos[j] = 1.f / (sqrtf(sb) + EPSF);
    g_rnb_nn[j]  = 1.f / (sqrtf(sb + EPSF) + EPSF);
}

// ---------------- main kernel helpers ------------------------------------------
static __device__ __forceinline__ void prefetch_chunk(uint32_t sB, const __nv_bfloat16* src, int tid) {
#pragma unroll
    for (int h = 0; h < 2; ++h) {
        int q = tid + h * 256;
        int k = q >> 4, seg = q & 15;
        uint32_t dst = sB + k * BSTR + seg * 16;
        const char* s = (const char*)(src + (size_t)k * HW) + seg * 16;
        asm volatile("cp.async.cg.shared.global [%0], [%1], 16;" :: "r"(dst), "l"(s));
    }
    asm volatile("cp.async.commit_group;" ::: "memory");
}

static __device__ __forceinline__ void compute_chunk(
    uint32_t sA, uint32_t sB, int warp_m, int warp_n, int L, int kbase, float acc[4][4][4])
{
#pragma unroll
    for (int kf = 0; kf < 2; ++kf) {
        uint32_t a[4][4], b[4][2];
        const uint32_t arow = warp_m * 64 + (L & 15);
        const uint32_t acol = kbase + kf * 16 + (L >> 4) * 8;
#pragma unroll
        for (int mf = 0; mf < 4; ++mf) {
            uint32_t addr = sA + (arow + mf * 16) * ASTR + acol * 2;
            asm volatile("ldmatrix.sync.aligned.m8n8.x4.shared.b16 {%0,%1,%2,%3}, [%4];"
                : "=r"(a[mf][0]), "=r"(a[mf][1]), "=r"(a[mf][2]), "=r"(a[mf][3]) : "r"(addr));
        }
#pragma unroll
        for (int nf = 0; nf < 4; ++nf) {
            uint32_t addr = sB + (kf * 16 + (L & 15)) * BSTR + (warp_n * 32 + nf * 8) * 2;
            asm volatile("ldmatrix.sync.aligned.m8n8.x2.trans.shared.b16 {%0,%1}, [%2];"
                : "=r"(b[nf][0]), "=r"(b[nf][1]) : "r"(addr));
        }
#pragma unroll
        for (int mf = 0; mf < 4; ++mf)
#pragma unroll
            for (int nf = 0; nf < 4; ++nf)
                asm volatile("mma.sync.aligned.m16n8k16.row.col.f32.bf16.bf16.f32 "
                    "{%0,%1,%2,%3}, {%4,%5,%6,%7}, {%8,%9}, {%0,%1,%2,%3};"
                    : "+f"(acc[mf][nf][0]), "+f"(acc[mf][nf][1]),
                      "+f"(acc[mf][nf][2]), "+f"(acc[mf][nf][3])
                    : "r"(a[mf][0]), "r"(a[mf][1]), "r"(a[mf][2]), "r"(a[mf][3]),
                      "r"(b[nf][0]), "r"(b[nf][1]));
    }
}

extern __shared__ __align__(16) char smem[];

__global__ __launch_bounds__(256, 1) void nnfm_main_kernel(const float* __restrict__ A) {
    const int tid = threadIdx.x;
    const int L = tid & 31;
    const int wid = tid >> 5;
    const int warp_m = wid >> 2;   // 0..1  (64 rows each)
    const int warp_n = wid & 3;    // 0..3  (32 cols each)
    const int ibase = blockIdx.x * 128;

    const uint32_t sbase = smem_u32(smem);
    const uint32_t sA = sbase;

    // kick off first B chunk copy immediately (overlaps A load)
    prefetch_chunk(sbase + SM_B0, g_bbf, tid);

    // Load A tile [k][i] -> SMEM [i][k] as bf16, padded rows. One-time.
    {
        const int i = tid & 127;
        const int kp = tid >> 7;   // 0/1
        char* dst = smem + (size_t)i * ASTR;
        const float* src = A + ibase + i;
#pragma unroll 4
        for (int k0 = 0; k0 < C; k0 += 4) {
            int k = k0 + kp * 2;
            float x0 = src[(size_t)k * HW];
            float x1 = src[(size_t)(k + 1) * HW];
            __nv_bfloat162 h = __floats2bfloat162_rn(x0, x1);
            *(uint32_t*)(dst + k * 2) = *reinterpret_cast<uint32_t*>(&h);
        }
    }
    __syncthreads();

    float best[8];
    int bj[8];
#pragma unroll
    for (int s = 0; s < 8; ++s) { best[s] = -3.4e38f; bj[s] = 0; }

    for (int jt = 0; jt < NJT; ++jt) {
        float acc[4][4][4];
#pragma unroll
        for (int mf = 0; mf < 4; ++mf)
#pragma unroll
            for (int nf = 0; nf < 4; ++nf)
#pragma unroll
                for (int r = 0; r < 4; ++r) acc[mf][nf][r] = 0.f;

        float rnv[4][2];
#pragma unroll
        for (int nf = 0; nf < 4; ++nf)
#pragma unroll
            for (int bb = 0; bb < 2; ++bb)
                rnv[nf][bb] = g_rnb_nn[jt * 128 + warp_n * 32 + nf * 8 + 2 * (L & 3) + bb];

        for (int c = 0; c < NCHK; ++c) {
            const int idx = jt * NCHK + c;
            if (idx + 1 < NJT * NCHK) {
                const int njt = (c == NCHK - 1) ? jt + 1 : jt;
                const int nc  = (c == NCHK - 1) ? 0 : c + 1;
                prefetch_chunk(((idx + 1) & 1) ? sbase + SM_B1 : sbase + SM_B0,
                               g_bbf + (size_t)(nc * 32) * HW + (size_t)njt * 128, tid);
                asm volatile("cp.async.wait_group 1;" ::: "memory");
            } else {
                asm volatile("cp.async.wait_group 0;" ::: "memory");
            }
            __syncthreads();
            compute_chunk(sA, (idx & 1) ? sbase + SM_B1 : sbase + SM_B0,
                          warp_m, warp_n, L, c * 32, acc);
            __syncthreads();
        }

        // fold tile into running argmax (j ascending; strict > keeps lowest j)
#pragma unroll
        for (int mf = 0; mf < 4; ++mf)
#pragma unroll
            for (int nf = 0; nf < 4; ++nf)
#pragma unroll
                for (int r = 0; r < 4; ++r) {
                    float t = acc[mf][nf][r] * rnv[nf][r & 1];
                    int slot = mf * 2 + (r >> 1);
                    if (t > best[slot]) {
                        best[slot] = t;
                        bj[slot] = jt * 128 + warp_n * 32 + nf * 8 + 2 * (L & 3) + (r & 1);
                    }
                }
    }

    // reduce across the 4 lanes sharing each row, then across warp_n via SMEM
    float* sBest = (float*)(smem + SM_RED);
    int*   sJ    = (int*)  (smem + SM_RED + 512 * 4);

#pragma unroll
    for (int slot = 0; slot < 8; ++slot) {
        float bb = best[slot];
        int jj = bj[slot];
#pragma unroll
        for (int off = 1; off < 4; off <<= 1) {
            float ob = __shfl_down_sync(0xffffffffu, bb, off, 4);
            int   oj = __shfl_down_sync(0xffffffffu, jj, off, 4);
            if (ob > bb || (ob == bb && oj < jj)) { bb = ob; jj = oj; }
        }
        if ((L & 3) == 0) {
            int mf = slot >> 1, half = slot & 1;
            int r = warp_m * 64 + mf * 16 + (L >> 2) + half * 8;
            sBest[r * 4 + warp_n] = bb;
            sJ   [r * 4 + warp_n] = jj;
        }
    }
    __syncthreads();
    if (tid < 128) {
        float bb = -3.4e38f;
        int jj = 0;
        for (int u = 0; u < 4; ++u) {
            float v = sBest[tid * 4 + u];
            int oj = sJ[tid * 4 + u];
            if (v > bb || (v == bb && oj < jj)) { bb = v; jj = oj; }
        }
        g_bjf[ibase + tid] = jj;
    }
}

// ---------------- fp32 rescore: lane=i (coalesced A), 4 k-quarters per row -----
__global__ void rescore_kernel(const float* __restrict__ A, const float* __restrict__ B) {
    __shared__ float part[256];
    const int il = threadIdx.x & 63;
    const int iq = threadIdx.x >> 6;     // k-quarter 0..3
    const int i = blockIdx.x * 64 + il;
    const int j = g_bjf[i];
    float s = 0.f;
    const float* ap = A + (size_t)(iq * 192) * HW + i;
    const float* bp = B + (size_t)(iq * 192) * HW + j;
#pragma unroll 8
    for (int kk = 0; kk < 192; ++kk) {
        s = fmaf(ap[(size_t)kk * HW], bp[(size_t)kk * HW], s);
    }
    part[threadIdx.x] = s;
    __syncthreads();
    if (iq == 0) {
        float tot = ((part[il] + part[il + 64]) + part[il + 128]) + part[il + 192];
        g_li[i] = 1.f - tot * g_rna_cos[i] * g_rnb_cos[j];
    }
}

// ---------------- finalize -----------------------------------------------------
__global__ void finalize_kernel(float* __restrict__ out) {
    __shared__ float red[256];
    int tid = threadIdx.x;
    float s = 0.f;
    for (int i = tid; i < HW; i += 256) s += g_li[i];
    red[tid] = s;
    __syncthreads();
    for (int off = 128; off > 0; off >>= 1) {
        if (tid < off) red[tid] += red[tid + off];
        __syncthreads();
    }
    if (tid == 0) out[0] = red[0] / (float)HW;
}

// ---------------- launch --------------------------------------------------------
extern "C" void kernel_launch(void* const* d_in, const int* in_sizes, int n_in,
                              void* d_out, int out_size) {
    const float* a = (const float*)d_in[0];
    const float* b = (const float*)d_in[1];
    float* out = (float*)d_out;

    cudaFuncSetAttribute(nnfm_main_kernel, cudaFuncAttributeMaxDynamicSharedMemorySize, SMEM_TOTAL);

    prep_kernel<<<dim3(HW / 512, 6), 256>>>(a, b);
    norms_fin_kernel<<<HW / 256, 256>>>();
    nnfm_main_kernel<<<128, 256, SMEM_TOTAL>>>(a);
    rescore_kernel<<<HW / 64, 256>>>(a, b);
    finalize_kernel<<<1, 256>>>(out);
}

// round 17
// speedup vs baseline: 1.0286x; 1.0286x over previous
#include <cuda_runtime.h>
#include <cuda_bf16.h>
#include <math.h>
#include <stdint.h>

#define HW 16384
#define C  768
#define EPSF 1e-8f

#define NJT   128       // j-tiles of 128 cols
#define NCHK  24        // k chunks of 32
#define ASTR  1552      // A_s row stride bytes (768*2 + 16 pad -> conflict-free ldmatrix)
#define ASZ   (128 * ASTR)          // 198656
#define BSTR  272       // B_s row stride bytes (128*2 + 16 pad)
#define BCHK  (32 * BSTR)           // 8704 per buffer
#define SM_B0 ASZ
#define SM_B1 (ASZ + BCHK)
#define SM_RED (ASZ + 2 * BCHK)     // reduction area: 512 best + 512 j
#define SMEM_TOTAL (SM_RED + 512 * 8)

// ---------------- scratch ------------------------------------------------------
__device__ __align__(16) __nv_bfloat16 g_bbf[(size_t)C * HW];  // B in bf16, [k][j]
__device__ float g_pa[6][HW];
__device__ float g_pb[6][HW];
__device__ float g_rna_cos[HW];
__device__ float g_rnb_cos[HW];
__device__ float g_rnb_nn[HW];
__device__ int   g_bjf[HW];
__device__ float g_li[HW];

static __device__ __forceinline__ uint32_t smem_u32(const void* p) {
    uint32_t a;
    asm("{ .reg .u64 t; cvta.to.shared.u64 t, %1; cvt.u32.u64 %0, t; }" : "=r"(a) : "l"(p));
    return a;
}

// ---------------- prep: convert B->bf16 + norm partials ------------------------
__global__ void prep_kernel(const float* __restrict__ A, const float* __restrict__ B) {
    int j = blockIdx.x * 256 + threadIdx.x;
    int kb = blockIdx.y;
    float sa = 0.f, sb = 0.f;
#pragma unroll 8
    for (int kk = 0; kk < 128; ++kk) {
        int k = kb * 128 + kk;
        float av = A[(size_t)k * HW + j];
        float bv = B[(size_t)k * HW + j];
        sa = fmaf(av, av, sa);
        sb = fmaf(bv, bv, sb);
        g_bbf[(size_t)k * HW + j] = __float2bfloat16(bv);
    }
    g_pa[kb][j] = sa;
    g_pb[kb][j] = sb;
}

__global__ void norms_fin_kernel() {
    int j = blockIdx.x * 256 + threadIdx.x;
    float sa = 0.f, sb = 0.f;
#pragma unroll
    for (int kb = 0; kb < 6; ++kb) { sa += g_pa[kb][j]; sb += g_pb[kb][j]; }
    g_rna_cos[j] = 1.f / (sqrtf(sa) + EPSF);
    g_rnb_cos[j] = 1.f / (sqrtf(sb) + EPSF);
    g_rnb_nn[j]  = 1.f / (sqrtf(sb + EPSF) + EPSF);
}

// ---------------- main kernel helpers ------------------------------------------
static __device__ __forceinline__ void prefetch_chunk(uint32_t sB, const __nv_bfloat16* src, int tid) {
#pragma unroll
    for (int h = 0; h < 2; ++h) {
        int q = tid + h * 256;
        int k = q >> 4, seg = q & 15;
        uint32_t dst = sB + k * BSTR + seg * 16;
        const char* s = (const char*)(src + (size_t)k * HW) + seg * 16;
        asm volatile("cp.async.ca.shared.global [%0], [%1], 16;" :: "r"(dst), "l"(s));
    }
    asm volatile("cp.async.commit_group;" ::: "memory");
}

static __device__ __forceinline__ void compute_chunk(
    uint32_t sA, uint32_t sB, int warp_m, int warp_n, int L, int kbase, float acc[4][4][4])
{
#pragma unroll
    for (int kf = 0; kf < 2; ++kf) {
        uint32_t a[4][4], b[4][2];
        const uint32_t arow = warp_m * 64 + (L & 15);
        const uint32_t acol = kbase + kf * 16 + (L >> 4) * 8;
#pragma unroll
        for (int mf = 0; mf < 4; ++mf) {
            uint32_t addr = sA + (arow + mf * 16) * ASTR + acol * 2;
            asm volatile("ldmatrix.sync.aligned.m8n8.x4.shared.b16 {%0,%1,%2,%3}, [%4];"
                : "=r"(a[mf][0]), "=r"(a[mf][1]), "=r"(a[mf][2]), "=r"(a[mf][3]) : "r"(addr));
        }
#pragma unroll
        for (int nf = 0; nf < 4; ++nf) {
            uint32_t addr = sB + (kf * 16 + (L & 15)) * BSTR + (warp_n * 32 + nf * 8) * 2;
            asm volatile("ldmatrix.sync.aligned.m8n8.x2.trans.shared.b16 {%0,%1}, [%2];"
                : "=r"(b[nf][0]), "=r"(b[nf][1]) : "r"(addr));
        }
#pragma unroll
        for (int mf = 0; mf < 4; ++mf)
#pragma unroll
            for (int nf = 0; nf < 4; ++nf)
                asm volatile("mma.sync.aligned.m16n8k16.row.col.f32.bf16.bf16.f32 "
                    "{%0,%1,%2,%3}, {%4,%5,%6,%7}, {%8,%9}, {%0,%1,%2,%3};"
                    : "+f"(acc[mf][nf][0]), "+f"(acc[mf][nf][1]),
                      "+f"(acc[mf][nf][2]), "+f"(acc[mf][nf][3])
                    : "r"(a[mf][0]), "r"(a[mf][1]), "r"(a[mf][2]), "r"(a[mf][3]),
                      "r"(b[nf][0]), "r"(b[nf][1]));
    }
}

extern __shared__ __align__(16) char smem[];

__global__ __launch_bounds__(256, 1) void nnfm_main_kernel(const float* __restrict__ A) {
    const int tid = threadIdx.x;
    const int L = tid & 31;
    const int wid = tid >> 5;
    const int warp_m = wid >> 2;   // 0..1  (64 rows each)
    const int warp_n = wid & 3;    // 0..3  (32 cols each)
    const int ibase = blockIdx.x * 128;

    const uint32_t sbase = smem_u32(smem);
    const uint32_t sA = sbase;

    // kick off first B chunk copy immediately (overlaps A load)
    prefetch_chunk(sbase + SM_B0, g_bbf, tid);

    // Load A tile [k][i] -> SMEM [i][k] as bf16, padded rows. One-time.
    {
        const int i = tid & 127;
        const int kp = tid >> 7;   // 0/1
        char* dst = smem + (size_t)i * ASTR;
        const float* src = A + ibase + i;
#pragma unroll 4
        for (int k0 = 0; k0 < C; k0 += 4) {
            int k = k0 + kp * 2;
            float x0 = src[(size_t)k * HW];
            float x1 = src[(size_t)(k + 1) * HW];
            __nv_bfloat162 h = __floats2bfloat162_rn(x0, x1);
            *(uint32_t*)(dst + k * 2) = *reinterpret_cast<uint32_t*>(&h);
        }
    }
    __syncthreads();

    float best[8];
    int bj[8];
#pragma unroll
    for (int s = 0; s < 8; ++s) { best[s] = -3.4e38f; bj[s] = 0; }

    for (int jt = 0; jt < NJT; ++jt) {
        float acc[4][4][4];
#pragma unroll
        for (int mf = 0; mf < 4; ++mf)
#pragma unroll
            for (int nf = 0; nf < 4; ++nf)
#pragma unroll
                for (int r = 0; r < 4; ++r) acc[mf][nf][r] = 0.f;

        float rnv[4][2];
#pragma unroll
        for (int nf = 0; nf < 4; ++nf)
#pragma unroll
            for (int bb = 0; bb < 2; ++bb)
                rnv[nf][bb] = g_rnb_nn[jt * 128 + warp_n * 32 + nf * 8 + 2 * (L & 3) + bb];

        for (int c = 0; c < NCHK; ++c) {
            const int idx = jt * NCHK + c;
            if (idx + 1 < NJT * NCHK) {
                const int njt = (c == NCHK - 1) ? jt + 1 : jt;
                const int nc  = (c == NCHK - 1) ? 0 : c + 1;
                prefetch_chunk(((idx + 1) & 1) ? sbase + SM_B1 : sbase + SM_B0,
                               g_bbf + (size_t)(nc * 32) * HW + (size_t)njt * 128, tid);
                asm volatile("cp.async.wait_group 1;" ::: "memory");
            } else {
                asm volatile("cp.async.wait_group 0;" ::: "memory");
            }
            __syncthreads();
            compute_chunk(sA, (idx & 1) ? sbase + SM_B1 : sbase + SM_B0,
                          warp_m, warp_n, L, c * 32, acc);
            __syncthreads();
        }

        // fold tile into running argmax (j ascending; strict > keeps lowest j)
#pragma unroll
        for (int mf = 0; mf < 4; ++mf)
#pragma unroll
            for (int nf = 0; nf < 4; ++nf)
#pragma unroll
                for (int r = 0; r < 4; ++r) {
                    float t = acc[mf][nf][r] * rnv[nf][r & 1];
                    int slot = mf * 2 + (r >> 1);
                    if (t > best[slot]) {
                        best[slot] = t;
                        bj[slot] = jt * 128 + warp_n * 32 + nf * 8 + 2 * (L & 3) + (r & 1);
                    }
                }
    }

    // reduce across the 4 lanes sharing each row, then across warp_n via SMEM
    float* sBest = (float*)(smem + SM_RED);
    int*   sJ    = (int*)  (smem + SM_RED + 512 * 4);

#pragma unroll
    for (int slot = 0; slot < 8; ++slot) {
        float bb = best[slot];
        int jj = bj[slot];
#pragma unroll
        for (int off = 1; off < 4; off <<= 1) {
            float ob = __shfl_down_sync(0xffffffffu, bb, off, 4);
            int   oj = __shfl_down_sync(0xffffffffu, jj, off, 4);
            if (ob > bb || (ob == bb && oj < jj)) { bb = ob; jj = oj; }
        }
        if ((L & 3) == 0) {
            int mf = slot >> 1, half = slot & 1;
            int r = warp_m * 64 + mf * 16 + (L >> 2) + half * 8;
            sBest[r * 4 + warp_n] = bb;
            sJ   [r * 4 + warp_n] = jj;
        }
    }
    __syncthreads();
    if (tid < 128) {
        float bb = -3.4e38f;
        int jj = 0;
        for (int u = 0; u < 4; ++u) {
            float v = sBest[tid * 4 + u];
            int oj = sJ[tid * 4 + u];
            if (v > bb || (v == bb && oj < jj)) { bb = v; jj = oj; }
        }
        g_bjf[ibase + tid] = jj;
    }
}

// ---------------- fp32 rescore: lane=i (coalesced A), 4 k-quarters per row -----
__global__ void rescore_kernel(const float* __restrict__ A, const float* __restrict__ B) {
    __shared__ float part[256];
    const int il = threadIdx.x & 63;
    const int iq = threadIdx.x >> 6;     // k-quarter 0..3
    const int i = blockIdx.x * 64 + il;
    const int j = g_bjf[i];
    float s = 0.f;
    const float* ap = A + (size_t)(iq * 192) * HW + i;
    const float* bp = B + (size_t)(iq * 192) * HW + j;
#pragma unroll 8
    for (int kk = 0; kk < 192; ++kk) {
        s = fmaf(ap[(size_t)kk * HW], bp[(size_t)kk * HW], s);
    }
    part[threadIdx.x] = s;
    __syncthreads();
    if (iq == 0) {
        float tot = ((part[il] + part[il + 64]) + part[il + 128]) + part[il + 192];
        g_li[i] = 1.f - tot * g_rna_cos[i] * g_rnb_cos[j];
    }
}

// ---------------- finalize -----------------------------------------------------
__global__ void finalize_kernel(float* __restrict__ out) {
    __shared__ float red[256];
    int tid = threadIdx.x;
    float s = 0.f;
    for (int i = tid; i < HW; i += 256) s += g_li[i];
    red[tid] = s;
    __syncthreads();
    for (int off = 128; off > 0; off >>= 1) {
        if (tid < off) red[tid] += red[tid + off];
        __syncthreads();
    }
    if (tid == 0) out[0] = red[0] / (float)HW;
}

// ---------------- launch --------------------------------------------------------
extern "C" void kernel_launch(void* const* d_in, const int* in_sizes, int n_in,
                              void* d_out, int out_size) {
    const float* a = (const float*)d_in[0];
    const float* b = (const float*)d_in[1];
    float* out = (float*)d_out;

    cudaFuncSetAttribute(nnfm_main_kernel, cudaFuncAttributeMaxDynamicSharedMemorySize, SMEM_TOTAL);

    prep_kernel<<<dim3(HW / 256, 6), 256>>>(a, b);
    norms_fin_kernel<<<HW / 256, 256>>>();
    nnfm_main_kernel<<<128, 256, SMEM_TOTAL>>>(a);
    rescore_kernel<<<HW / 64, 256>>>(a, b);
    finalize_kernel<<<1, 256>>>(out);
}